// round 15
// baseline (speedup 1.0000x reference)
#include <cuda_runtime.h>
#include <cuda_fp16.h>

typedef unsigned long long ull;

#define N_NODES 100000
#define N_EDGES 1600000
#define IN_DIM  64
#define HID     128
#define OUT_DIM 16
#define MT      128         // GEMM M-tile
#define CHUNK   512
#define NCHUNK  ((N_NODES + CHUNK - 1) / CHUNK)   // 196

// ---------------- scratch (device globals; no allocation allowed) ----------
__device__ __align__(16) int   g_deg[N_NODES];
__device__ __align__(16) int   g_rowptr[N_NODES];
__device__ __align__(16) int   g_pos[N_NODES];
__device__ __align__(16) int   g_col[N_EDGES];
__device__ __align__(16) int   g_chunk[NCHUNK];
__device__ __align__(16) float g_agg1[N_NODES * IN_DIM];
__device__ __align__(16) float g_h1pre[N_NODES * HID];    // x @ w1r + b1l
__device__ __align__(16) float g_h1[N_NODES * HID];       // relu(normalize(l1)) fp32
__device__ __align__(16) float g_agg2[N_NODES * HID];     // BN'ed neighbor mean
__device__ __align__(16) __half2 g_xh[N_NODES * 32];      // fp16 copy of x  (64 dims)
__device__ __align__(16) __half2 g_h1h[N_NODES * 64];     // fp16 copy of h1 (128 dims)
__device__ __align__(16) float g_bnsum[HID];
__device__ __align__(16) float g_bnsq[HID];
__device__ __align__(16) float g_bnscale[HID];
__device__ __align__(16) float g_bnshift[HID];

// ---------------- packed f32x2 helpers --------------------------------------
__device__ __forceinline__ ull pack2(float v) {
    ull r; asm("mov.b64 %0, {%1, %1};" : "=l"(r) : "f"(v)); return r;
}
__device__ __forceinline__ float2 unpack2(ull v) {
    float2 f; asm("mov.b64 {%0, %1}, %2;" : "=f"(f.x), "=f"(f.y) : "l"(v)); return f;
}
__device__ __forceinline__ void fma2(ull& d, ull a, ull b) {
    asm("fma.rn.f32x2 %0, %1, %2, %0;" : "+l"(d) : "l"(a), "l"(b));
}

// ---------------- shared GEMM inner loop ------------------------------------
// Thread (r, c): rows r*4..r*4+3, float columns [c*16, c*16+16) = ull [c*8, c*8+8).
// A: float4 per row per 4k (LDS.128). W: 4x ulonglong2 per k (LDS.128).
template<int KDIM>
__device__ __forceinline__ void gemm_tile(
    const float* __restrict__ a0, const float* __restrict__ a1,
    const float* __restrict__ a2, const float* __restrict__ a3,
    const float* __restrict__ sW, int c, ull acc[4][8])
{
    #pragma unroll 2
    for (int k4 = 0; k4 < KDIM; k4 += 4) {
        float4 A0 = *(const float4*)(a0 + k4);
        float4 A1 = *(const float4*)(a1 + k4);
        float4 A2 = *(const float4*)(a2 + k4);
        float4 A3 = *(const float4*)(a3 + k4);
        const float* ap0 = (const float*)&A0;
        const float* ap1 = (const float*)&A1;
        const float* ap2 = (const float*)&A2;
        const float* ap3 = (const float*)&A3;
        #pragma unroll
        for (int kk = 0; kk < 4; kk++) {
            const ulonglong2* wr = (const ulonglong2*)(sW + (k4 + kk) * HID) + c * 4;
            ulonglong2 w0 = wr[0];
            ulonglong2 w1 = wr[1];
            ulonglong2 w2 = wr[2];
            ulonglong2 w3 = wr[3];
            ull va0 = pack2(ap0[kk]);
            ull va1 = pack2(ap1[kk]);
            ull va2 = pack2(ap2[kk]);
            ull va3 = pack2(ap3[kk]);
            fma2(acc[0][0], va0, w0.x); fma2(acc[0][1], va0, w0.y);
            fma2(acc[0][2], va0, w1.x); fma2(acc[0][3], va0, w1.y);
            fma2(acc[0][4], va0, w2.x); fma2(acc[0][5], va0, w2.y);
            fma2(acc[0][6], va0, w3.x); fma2(acc[0][7], va0, w3.y);
            fma2(acc[1][0], va1, w0.x); fma2(acc[1][1], va1, w0.y);
            fma2(acc[1][2], va1, w1.x); fma2(acc[1][3], va1, w1.y);
            fma2(acc[1][4], va1, w2.x); fma2(acc[1][5], va1, w2.y);
            fma2(acc[1][6], va1, w3.x); fma2(acc[1][7], va1, w3.y);
            fma2(acc[2][0], va2, w0.x); fma2(acc[2][1], va2, w0.y);
            fma2(acc[2][2], va2, w1.x); fma2(acc[2][3], va2, w1.y);
            fma2(acc[2][4], va2, w2.x); fma2(acc[2][5], va2, w2.y);
            fma2(acc[2][6], va2, w3.x); fma2(acc[2][7], va2, w3.y);
            fma2(acc[3][0], va3, w0.x); fma2(acc[3][1], va3, w0.y);
            fma2(acc[3][2], va3, w1.x); fma2(acc[3][3], va3, w1.y);
            fma2(acc[3][4], va3, w2.x); fma2(acc[3][5], va3, w2.y);
            fma2(acc[3][6], va3, w3.x); fma2(acc[3][7], va3, w3.y);
        }
    }
}

// ---------------- zero + fp16 convert of x ----------------------------------
__global__ void zero_kernel(const float* __restrict__ x) {
    int i = blockIdx.x * blockDim.x + threadIdx.x;
    if (i < N_NODES) g_deg[i] = 0;
    if (i < HID) { g_bnsum[i] = 0.f; g_bnsq[i] = 0.f; }
    if (i < N_NODES * 16) {
        float4 v = ((const float4*)x)[i];
        union { __half2 h[2]; uint2 u; } pk;
        pk.h[0] = __floats2half2_rn(v.x, v.y);
        pk.h[1] = __floats2half2_rn(v.z, v.w);
        ((uint2*)g_xh)[i] = pk.u;
    }
}

__global__ void hist_kernel(const int* __restrict__ ei) {
    int e = blockIdx.x * blockDim.x + threadIdx.x;
    if (e < N_EDGES) atomicAdd(&g_deg[ei[N_EDGES + e]], 1);
}

__global__ void scan_chunk_kernel() {
    __shared__ int s[CHUNK];
    int t = threadIdx.x;
    int i = blockIdx.x * CHUNK + t;
    int v = (i < N_NODES) ? g_deg[i] : 0;
    s[t] = v;
    __syncthreads();
    for (int off = 1; off < CHUNK; off <<= 1) {
        int add = (t >= off) ? s[t - off] : 0;
        __syncthreads();
        s[t] += add;
        __syncthreads();
    }
    if (i < N_NODES) g_rowptr[i] = s[t] - v;
    if (t == CHUNK - 1) g_chunk[blockIdx.x] = s[t];
}

// ---------------- gemm_self: h1pre = x @ w1r + b1l  (PROBE SLOT #4) ---------
#define KSS 68
#define SMEMS ((IN_DIM*HID + MT*KSS + HID) * 4)

__global__ __launch_bounds__(256, 2) void gemm_self_kernel(
    const float* __restrict__ x,
    const float* __restrict__ w1r,
    const float* __restrict__ b1l)
{
    extern __shared__ float sm[];
    float* sW = sm;                  // [64][128]
    float* sA = sW + IN_DIM * HID;   // [128][68]
    float* sB = sA + MT * KSS;

    int tx = threadIdx.x;
    for (int i = tx; i < IN_DIM * HID / 4; i += 256)
        ((float4*)sW)[i] = ((const float4*)w1r)[i];
    if (tx < HID) sB[tx] = b1l[tx];

    int nb = blockIdx.x * MT;
    for (int i = tx; i < MT * 16; i += 256) {
        int row = i >> 4, q = i & 15;
        int n = nb + row;
        float4 vx = make_float4(0.f, 0.f, 0.f, 0.f);
        if (n < N_NODES) vx = ((const float4*)x)[n * 16 + q];
        *(float4*)(sA + row * KSS + q * 4) = vx;
    }
    __syncthreads();

    int c = tx & 7, r = tx >> 3;
    ull acc[4][8];
    #pragma unroll
    for (int j = 0; j < 8; j++) {
        ull b = ((const ull*)sB)[c * 8 + j];
        acc[0][j] = b; acc[1][j] = b; acc[2][j] = b; acc[3][j] = b;
    }

    gemm_tile<IN_DIM>(sA + (r * 4 + 0) * KSS, sA + (r * 4 + 1) * KSS,
                      sA + (r * 4 + 2) * KSS, sA + (r * 4 + 3) * KSS,
                      sW, c, acc);

    #pragma unroll
    for (int i = 0; i < 4; i++) {
        int n = nb + r * 4 + i;
        if (n < N_NODES) {
            ull* dst = (ull*)(g_h1pre + (size_t)n * HID);
            #pragma unroll
            for (int j = 0; j < 8; j++) dst[c * 8 + j] = acc[i][j];
        }
    }
}

__global__ void scan_tops_kernel() {
    __shared__ int s[256];
    int t = threadIdx.x;
    int v = (t < NCHUNK) ? g_chunk[t] : 0;
    s[t] = v;
    __syncthreads();
    for (int off = 1; off < 256; off <<= 1) {
        int add = (t >= off) ? s[t - off] : 0;
        __syncthreads();
        s[t] += add;
        __syncthreads();
    }
    if (t < NCHUNK) g_chunk[t] = s[t] - v;
}

__global__ void add_off_kernel() {
    int i = blockIdx.x * blockDim.x + threadIdx.x;
    if (i < N_NODES) {
        int rp = g_rowptr[i] + g_chunk[i / CHUNK];
        g_rowptr[i] = rp;
        g_pos[i] = rp;
    }
}

__global__ void fill_kernel(const int* __restrict__ ei) {
    int e = blockIdx.x * blockDim.x + threadIdx.x;
    if (e < N_EDGES) {
        int src = ei[e];
        int dst = ei[N_EDGES + e];
        int p = atomicAdd(&g_pos[dst], 1);
        g_col[p] = src;
    }
}

// ---------------- gather 1: warp per node, mean of x16[neighbors] -----------
__global__ __launch_bounds__(256) void gather1_kernel() {
    int warp = threadIdx.x >> 5, lane = threadIdx.x & 31;
    int n = blockIdx.x * 8 + warp;
    if (n >= N_NODES) return;
    int d = g_deg[n], st = g_rowptr[n];
    float ax = 0.f, ay = 0.f;
    for (int base = 0; base < d; base += 32) {
        int m = min(d - base, 32);
        int ci = (lane < m) ? g_col[st + base + lane] : 0;
        int j = 0;
        for (; j + 8 <= m; j += 8) {
            int ss[8];
            #pragma unroll
            for (int u = 0; u < 8; u++) ss[u] = __shfl_sync(0xffffffffu, ci, j + u);
            __half2 v[8];
            #pragma unroll
            for (int u = 0; u < 8; u++) v[u] = g_xh[ss[u] * 32 + lane];
            #pragma unroll
            for (int u = 0; u < 8; u++) {
                float2 f = __half22float2(v[u]);
                ax += f.x; ay += f.y;
            }
        }
        for (; j < m; j++) {
            int s = __shfl_sync(0xffffffffu, ci, j);
            float2 f = __half22float2(g_xh[s * 32 + lane]);
            ax += f.x; ay += f.y;
        }
    }
    float rc = 1.0f / fmaxf((float)d, 1.0f);
    ((float2*)g_agg1)[n * 32 + lane] = make_float2(ax * rc, ay * rc);
}

// ---------------- GEMM 1b: agg @ w1l + h1pre, L2norm, relu, BN stats --------
#define SMEMG1 ((IN_DIM*HID + MT*KSS + 2*HID) * 4)

__global__ __launch_bounds__(256, 2) void gemm1_kernel(
    const float* __restrict__ w1l)
{
    extern __shared__ float sm[];
    float* sW   = sm;                  // [64][128]
    float* sA   = sW + IN_DIM * HID;   // [128][68]
    float* sSum = sA + MT * KSS;
    float* sSq  = sSum + HID;

    int tx = threadIdx.x;
    for (int i = tx; i < IN_DIM * HID / 4; i += 256)
        ((float4*)sW)[i] = ((const float4*)w1l)[i];
    if (tx < HID) { sSum[tx] = 0.f; sSq[tx] = 0.f; }

    int nb = blockIdx.x * MT;
    for (int i = tx; i < MT * 16; i += 256) {
        int row = i >> 4, q = i & 15;
        int n = nb + row;
        float4 va = make_float4(0.f, 0.f, 0.f, 0.f);
        if (n < N_NODES) va = ((const float4*)g_agg1)[n * 16 + q];
        *(float4*)(sA + row * KSS + q * 4) = va;
    }
    __syncthreads();

    int c = tx & 7, r = tx >> 3;
    ull acc[4][8];
    #pragma unroll
    for (int i = 0; i < 4; i++) {
        int n = nb + r * 4 + i;
        const ull* src = (const ull*)(g_h1pre + (size_t)(n < N_NODES ? n : 0) * HID);
        #pragma unroll
        for (int j = 0; j < 8; j++) acc[i][j] = src[c * 8 + j];
    }

    gemm_tile<IN_DIM>(sA + (r * 4 + 0) * KSS, sA + (r * 4 + 1) * KSS,
                      sA + (r * 4 + 2) * KSS, sA + (r * 4 + 3) * KSS,
                      sW, c, acc);

    // epilogue: per-node L2 norm, relu, store h1 (fp32+fp16), BN col stats
    // thread columns: c*16 + 2j, c*16 + 2j + 1
    float cs[16], cq[16];
    #pragma unroll
    for (int t = 0; t < 16; t++) { cs[t] = 0.f; cq[t] = 0.f; }

    #pragma unroll
    for (int i = 0; i < 4; i++) {
        float2 p[8];
        float ss = 0.f;
        #pragma unroll
        for (int j = 0; j < 8; j++) {
            p[j] = unpack2(acc[i][j]);
            ss += p[j].x * p[j].x + p[j].y * p[j].y;
        }
        ss += __shfl_xor_sync(0xffffffffu, ss, 1);
        ss += __shfl_xor_sync(0xffffffffu, ss, 2);
        ss += __shfl_xor_sync(0xffffffffu, ss, 4);
        float inv = 1.0f / fmaxf(sqrtf(ss), 1e-12f);
        int n = nb + r * 4 + i;
        bool ok = (n < N_NODES);
        #pragma unroll
        for (int j = 0; j < 8; j++) {
            float hx = fmaxf(p[j].x * inv, 0.f);
            float hy = fmaxf(p[j].y * inv, 0.f);
            if (!ok) { hx = 0.f; hy = 0.f; }
            else {
                *(float2*)(g_h1 + (size_t)n * HID + c * 16 + 2 * j) = make_float2(hx, hy);
                g_h1h[n * 64 + c * 8 + j] = __floats2half2_rn(hx, hy);
            }
            cs[2 * j] += hx; cs[2 * j + 1] += hy;
            cq[2 * j] += hx * hx; cq[2 * j + 1] += hy * hy;
        }
    }
    #pragma unroll
    for (int t = 0; t < 16; t++) {
        cs[t] += __shfl_xor_sync(0xffffffffu, cs[t], 8);
        cs[t] += __shfl_xor_sync(0xffffffffu, cs[t], 16);
        cq[t] += __shfl_xor_sync(0xffffffffu, cq[t], 8);
        cq[t] += __shfl_xor_sync(0xffffffffu, cq[t], 16);
    }
    if ((tx & 31) < 8) {
        #pragma unroll
        for (int j = 0; j < 8; j++) {
            atomicAdd(&sSum[c * 16 + 2 * j],     cs[2 * j]);
            atomicAdd(&sSum[c * 16 + 2 * j + 1], cs[2 * j + 1]);
            atomicAdd(&sSq[c * 16 + 2 * j],      cq[2 * j]);
            atomicAdd(&sSq[c * 16 + 2 * j + 1],  cq[2 * j + 1]);
        }
    }
    __syncthreads();
    if (tx < HID) {
        atomicAdd(&g_bnsum[tx], sSum[tx]);
        atomicAdd(&g_bnsq[tx], sSq[tx]);
    }
}

// ---------------- BN finalize ----------------
__global__ void bn_finalize_kernel(const float* __restrict__ gamma,
                                   const float* __restrict__ beta)
{
    int j = threadIdx.x;
    if (j < HID) {
        float mean = g_bnsum[j] / (float)N_NODES;
        float var  = g_bnsq[j] / (float)N_NODES - mean * mean;
        float inv  = rsqrtf(var + 1e-5f);
        float sc   = gamma[j] * inv;
        g_bnscale[j] = sc;
        g_bnshift[j] = beta[j] - mean * sc;
    }
}

// ---------------- gather 2: warp per node, fp16 h1, BN fused ----------------
__global__ __launch_bounds__(256) void gather2_kernel() {
    int warp = threadIdx.x >> 5, lane = threadIdx.x & 31;
    int n = blockIdx.x * 8 + warp;
    if (n >= N_NODES) return;
    int d = g_deg[n], st = g_rowptr[n];
    const uint2* h2p = (const uint2*)g_h1h;
    float4 acc = make_float4(0.f, 0.f, 0.f, 0.f);
    for (int base = 0; base < d; base += 32) {
        int m = min(d - base, 32);
        int ci = (lane < m) ? g_col[st + base + lane] : 0;
        int j = 0;
        for (; j + 4 <= m; j += 4) {
            int ss[4];
            #pragma unroll
            for (int u = 0; u < 4; u++) ss[u] = __shfl_sync(0xffffffffu, ci, j + u);
            uint2 rv[4];
            #pragma unroll
            for (int u = 0; u < 4; u++) rv[u] = h2p[ss[u] * 32 + lane];
            #pragma unroll
            for (int u = 0; u < 4; u++) {
                union { uint2 u2; __half2 h[2]; } pk; pk.u2 = rv[u];
                float2 f0 = __half22float2(pk.h[0]);
                float2 f1 = __half22float2(pk.h[1]);
                acc.x += f0.x; acc.y += f0.y; acc.z += f1.x; acc.w += f1.y;
            }
        }
        for (; j < m; j++) {
            int s = __shfl_sync(0xffffffffu, ci, j);
            union { uint2 u2; __half2 h[2]; } pk; pk.u2 = h2p[s * 32 + lane];
            float2 f0 = __half22float2(pk.h[0]);
            float2 f1 = __half22float2(pk.h[1]);
            acc.x += f0.x; acc.y += f0.y; acc.z += f1.x; acc.w += f1.y;
        }
    }
    float rc = 1.0f / fmaxf((float)d, 1.0f);
    float flag = (d > 0) ? 1.0f : 0.0f;
    // fp16 h1 dims at lane: [4*lane, 4*lane+4) in the h1h packing = cols 4*lane..
    float4 sc = ((const float4*)g_bnscale)[lane];
    float4 sh = ((const float4*)g_bnshift)[lane];
    float4 ag;
    ag.x = sc.x * acc.x * rc + sh.x * flag;
    ag.y = sc.y * acc.y * rc + sh.y * flag;
    ag.z = sc.z * acc.z * rc + sh.z * flag;
    ag.w = sc.w * acc.w * rc + sh.w * flag;
    ((float4*)g_agg2)[n * 32 + lane] = ag;
}

// ---------------- GEMM 2: [agg2|BN(h1)] @ [w2l;w2r] + b, L2norm, FC ---------
#define KS1 132
#define SMEMG2 ((HID*HID + MT*KS1 + HID*OUT_DIM + 3*HID + OUT_DIM) * 4)

__global__ __launch_bounds__(256) void gemm2_kernel(
    const float* __restrict__ w2l,
    const float* __restrict__ b2l,
    const float* __restrict__ w2r,
    const float* __restrict__ wfc,
    const float* __restrict__ bfc,
    float* __restrict__ out)
{
    extern __shared__ float sm[];
    float* sW   = sm;                    // [128][128] streamed: w2l then w2r
    float* sA   = sW + HID * HID;        // [128][132] streamed: agg2 then BN(h1)
    float* sWfc = sA + MT * KS1;         // [128][16]
    float* sB   = sWfc + HID * OUT_DIM;
    float* sSc  = sB + HID;
    float* sSh  = sSc + HID;
    float* sBfc = sSh + HID;

    int tx = threadIdx.x;
    if (tx < HID) {
        sB[tx]  = b2l[tx];
        sSc[tx] = g_bnscale[tx];
        sSh[tx] = g_bnshift[tx];
    }
    if (tx < OUT_DIM) sBfc[tx] = bfc[tx];
    for (int i = tx; i < HID * HID / 4; i += 256)
        ((float4*)sW)[i] = ((const float4*)w2l)[i];
    for (int i = tx; i < HID * OUT_DIM / 4; i += 256)
        ((float4*)sWfc)[i] = ((const float4*)wfc)[i];

    int nb = blockIdx.x * MT;
    for (int i = tx; i < MT * 32; i += 256) {
        int row = i >> 5, q = i & 31;
        int n = nb + row;
        float4 v = make_float4(0.f, 0.f, 0.f, 0.f);
        if (n < N_NODES) v = ((const float4*)g_agg2)[n * 32 + q];
        *(float4*)(sA + row * KS1 + q * 4) = v;
    }
    __syncthreads();

    int c = tx & 7, r = tx >> 3;
    ull acc[4][8];
    #pragma unroll
    for (int j = 0; j < 8; j++) {
        ull b = ((const ull*)sB)[c * 8 + j];
        acc[0][j] = b; acc[1][j] = b; acc[2][j] = b; acc[3][j] = b;
    }

    #pragma unroll
    for (int pass = 0; pass < 2; pass++) {
        if (pass == 1) {
            __syncthreads();
            for (int i = tx; i < HID * HID / 4; i += 256)
                ((float4*)sW)[i] = ((const float4*)w2r)[i];
            for (int i = tx; i < MT * 32; i += 256) {
                int row = i >> 5, q = i & 31;
                int n = nb + row;
                float4 h = make_float4(0.f, 0.f, 0.f, 0.f);
                if (n < N_NODES) h = ((const float4*)g_h1)[n * 32 + q];
                float4 sc = ((const float4*)sSc)[q];
                float4 sh = ((const float4*)sSh)[q];
                float4 v;
                v.x = sc.x * h.x + sh.x;
                v.y = sc.y * h.y + sh.y;
                v.z = sc.z * h.z + sh.z;
                v.w = sc.w * h.w + sh.w;
                *(float4*)(sA + row * KS1 + q * 4) = v;
            }
            __syncthreads();
        }
        gemm_tile<HID>(sA + (r * 4 + 0) * KS1, sA + (r * 4 + 1) * KS1,
                       sA + (r * 4 + 2) * KS1, sA + (r * 4 + 3) * KS1,
                       sW, c, acc);
    }

    // L2 normalize each node row
    float2 p[4][8];
    #pragma unroll
    for (int i = 0; i < 4; i++) {
        float ss = 0.f;
        #pragma unroll
        for (int j = 0; j < 8; j++) {
            p[i][j] = unpack2(acc[i][j]);
            ss += p[i][j].x * p[i][j].x + p[i][j].y * p[i][j].y;
        }
        ss += __shfl_xor_sync(0xffffffffu, ss, 1);
        ss += __shfl_xor_sync(0xffffffffu, ss, 2);
        ss += __shfl_xor_sync(0xffffffffu, ss, 4);
        float inv = 1.0f / fmaxf(sqrtf(ss), 1e-12f);
        #pragma unroll
        for (int j = 0; j < 8; j++) { p[i][j].x *= inv; p[i][j].y *= inv; }
    }
    __syncthreads();

    float* sH = sA;    // [128][132]
    #pragma unroll
    for (int i = 0; i < 4; i++)
        #pragma unroll
        for (int j = 0; j < 8; j++)
            *(float2*)(sH + (r * 4 + i) * KS1 + c * 16 + 2 * j) = p[i][j];
    __syncthreads();

    int node = tx >> 1;
    int half = tx & 1;
    int n = nb + node;
    if (n < N_NODES) {
        float y[8];
        #pragma unroll
        for (int t = 0; t < 8; t++) y[t] = sBfc[half * 8 + t];
        const float* h = sH + node * KS1;
        #pragma unroll 4
        for (int j2 = 0; j2 < HID; j2++) {
            float hv = h[j2];
            float4 w0 = *(const float4*)(sWfc + j2 * OUT_DIM + half * 8);
            float4 w1 = *(const float4*)(sWfc + j2 * OUT_DIM + half * 8 + 4);
            y[0] += hv * w0.x; y[1] += hv * w0.y; y[2] += hv * w0.z; y[3] += hv * w0.w;
            y[4] += hv * w1.x; y[5] += hv * w1.y; y[6] += hv * w1.z; y[7] += hv * w1.w;
        }
        *(float4*)(out + (size_t)n * OUT_DIM + half * 8)     = make_float4(y[0], y[1], y[2], y[3]);
        *(float4*)(out + (size_t)n * OUT_DIM + half * 8 + 4) = make_float4(y[4], y[5], y[6], y[7]);
    }
}

// ---------------- launch ----------------------------------------------------
extern "C" void kernel_launch(void* const* d_in, const int* in_sizes, int n_in,
                              void* d_out, int out_size)
{
    const float* x     = (const float*)d_in[0];
    const int*   ei    = (const int*)d_in[1];
    const float* w1l   = (const float*)d_in[2];
    const float* b1l   = (const float*)d_in[3];
    const float* w1r   = (const float*)d_in[4];
    const float* gamma = (const float*)d_in[5];
    const float* beta  = (const float*)d_in[6];
    const float* w2l   = (const float*)d_in[7];
    const float* b2l   = (const float*)d_in[8];
    const float* w2r   = (const float*)d_in[9];
    const float* wfc   = (const float*)d_in[10];
    const float* bfc   = (const float*)d_in[11];
    float* out = (float*)d_out;

    cudaFuncSetAttribute(gemm_self_kernel, cudaFuncAttributeMaxDynamicSharedMemorySize, SMEMS);
    cudaFuncSetAttribute(gemm1_kernel, cudaFuncAttributeMaxDynamicSharedMemorySize, SMEMG1);
    cudaFuncSetAttribute(gemm2_kernel, cudaFuncAttributeMaxDynamicSharedMemorySize, SMEMG2);

    int ng = (N_NODES + 255) / 256;        // 391
    int eg = (N_EDGES + 255) / 256;        // 6250
    int gg = (N_NODES + 7) / 8;            // 12500
    int mg = (N_NODES + MT - 1) / MT;      // 782

    zero_kernel<<<eg, 256>>>(x);                        // #1
    hist_kernel<<<eg, 256>>>(ei);                       // #2
    scan_chunk_kernel<<<NCHUNK, CHUNK>>>();             // #3
    gemm_self_kernel<<<mg, 256, SMEMS>>>(x, w1r, b1l);  // #4  <-- profiled slot
    scan_tops_kernel<<<1, 256>>>();                     // #5
    add_off_kernel<<<ng, 256>>>();                      // #6
    fill_kernel<<<eg, 256>>>(ei);                       // #7
    gather1_kernel<<<gg, 256>>>();                      // #8
    gemm1_kernel<<<mg, 256, SMEMG1>>>(w1l);             // #9
    bn_finalize_kernel<<<1, 128>>>(gamma, beta);        // #10
    gather2_kernel<<<gg, 256>>>();                      // #11
    gemm2_kernel<<<mg, 256, SMEMG2>>>(w2l, b2l, w2r, wfc, bfc, out);  // #12
}

// round 17
// speedup vs baseline: 1.8939x; 1.8939x over previous
#include <cuda_runtime.h>
#include <cuda_fp16.h>

typedef unsigned long long ull;

#define N_NODES 100000
#define N_EDGES 1600000
#define IN_DIM  64
#define HID     128
#define OUT_DIM 16
#define MT      128         // GEMM M-tile
#define CHUNK   512
#define NCHUNK  ((N_NODES + CHUNK - 1) / CHUNK)   // 196

// ---------------- scratch (device globals; no allocation allowed) ----------
__device__ __align__(16) int   g_deg[N_NODES];
__device__ __align__(16) int   g_rowptr[N_NODES];
__device__ __align__(16) int   g_pos[N_NODES];
__device__ __align__(16) int   g_col[N_EDGES];
__device__ __align__(16) int   g_chunk[NCHUNK];
__device__ __align__(16) float g_agg1[N_NODES * IN_DIM];
__device__ __align__(16) float g_h1pre[N_NODES * HID];    // x @ w1r + b1l
__device__ __align__(16) float g_h1[N_NODES * HID];       // relu(normalize(l1)) fp32
__device__ __align__(16) float g_agg2[N_NODES * HID];     // BN'ed neighbor mean
__device__ __align__(16) __half2 g_xh[N_NODES * 32];      // fp16 copy of x  (64 dims)
__device__ __align__(16) __half2 g_h1h[N_NODES * 64];     // fp16 copy of h1 (128 dims)
__device__ __align__(16) float g_bnsum[HID];
__device__ __align__(16) float g_bnsq[HID];
__device__ __align__(16) float g_bnscale[HID];
__device__ __align__(16) float g_bnshift[HID];

// ---------------- packed f32x2 helpers --------------------------------------
__device__ __forceinline__ ull pack2(float v) {
    ull r; asm("mov.b64 %0, {%1, %1};" : "=l"(r) : "f"(v)); return r;
}
__device__ __forceinline__ float2 unpack2(ull v) {
    float2 f; asm("mov.b64 {%0, %1}, %2;" : "=f"(f.x), "=f"(f.y) : "l"(v)); return f;
}
__device__ __forceinline__ void fma2(ull& d, ull a, ull b) {
    asm("fma.rn.f32x2 %0, %1, %2, %0;" : "+l"(d) : "l"(a), "l"(b));
}

// ---------------- shared GEMM inner loop ------------------------------------
// R14 layout: thread c owns ull columns {c, c+8, ..., c+56} (W read via LDS.64,
// conflict-free broadcast). A read as float4 per row per 4 k-steps, components
// accessed EXPLICITLY (.x/.y/.z/.w) so they stay in registers.
#define GEMM_K_STEP(kk, A0c, A1c, A2c, A3c)                                    \
    {                                                                          \
        const ull* wr = (const ull*)(sW + (k4 + kk) * HID);                    \
        ull va0 = pack2(A0c);                                                  \
        ull va1 = pack2(A1c);                                                  \
        ull va2 = pack2(A2c);                                                  \
        ull va3 = pack2(A3c);                                                  \
        _Pragma("unroll")                                                      \
        for (int j = 0; j < 8; j++) {                                          \
            ull w = wr[c + 8 * j];                                             \
            fma2(acc[0][j], va0, w);                                           \
            fma2(acc[1][j], va1, w);                                           \
            fma2(acc[2][j], va2, w);                                           \
            fma2(acc[3][j], va3, w);                                           \
        }                                                                      \
    }

#define GEMM_LOOP(KDIM)                                                        \
    _Pragma("unroll 2")                                                        \
    for (int k4 = 0; k4 < (KDIM); k4 += 4) {                                   \
        float4 A0 = *(const float4*)(a0 + k4);                                 \
        float4 A1 = *(const float4*)(a1 + k4);                                 \
        float4 A2 = *(const float4*)(a2 + k4);                                 \
        float4 A3 = *(const float4*)(a3 + k4);                                 \
        GEMM_K_STEP(0, A0.x, A1.x, A2.x, A3.x)                                 \
        GEMM_K_STEP(1, A0.y, A1.y, A2.y, A3.y)                                 \
        GEMM_K_STEP(2, A0.z, A1.z, A2.z, A3.z)                                 \
        GEMM_K_STEP(3, A0.w, A1.w, A2.w, A3.w)                                 \
    }

// ---------------- zero + fp16 convert of x ----------------------------------
__global__ void zero_kernel(const float* __restrict__ x) {
    int i = blockIdx.x * blockDim.x + threadIdx.x;
    if (i < N_NODES) g_deg[i] = 0;
    if (i < HID) { g_bnsum[i] = 0.f; g_bnsq[i] = 0.f; }
    if (i < N_NODES * 16) {
        float4 v = ((const float4*)x)[i];
        union { __half2 h[2]; uint2 u; } pk;
        pk.h[0] = __floats2half2_rn(v.x, v.y);
        pk.h[1] = __floats2half2_rn(v.z, v.w);
        ((uint2*)g_xh)[i] = pk.u;
    }
}

__global__ void hist_kernel(const int* __restrict__ ei) {
    int e = blockIdx.x * blockDim.x + threadIdx.x;
    if (e < N_EDGES) atomicAdd(&g_deg[ei[N_EDGES + e]], 1);
}

__global__ void scan_chunk_kernel() {
    __shared__ int s[CHUNK];
    int t = threadIdx.x;
    int i = blockIdx.x * CHUNK + t;
    int v = (i < N_NODES) ? g_deg[i] : 0;
    s[t] = v;
    __syncthreads();
    for (int off = 1; off < CHUNK; off <<= 1) {
        int add = (t >= off) ? s[t - off] : 0;
        __syncthreads();
        s[t] += add;
        __syncthreads();
    }
    if (i < N_NODES) g_rowptr[i] = s[t] - v;
    if (t == CHUNK - 1) g_chunk[blockIdx.x] = s[t];
}

// ---------------- gemm_self: h1pre = x @ w1r + b1l  (PROBE SLOT #4) ---------
#define KSS 68
#define SMEMS ((IN_DIM*HID + MT*KSS + HID) * 4)

__global__ __launch_bounds__(256, 2) void gemm_self_kernel(
    const float* __restrict__ x,
    const float* __restrict__ w1r,
    const float* __restrict__ b1l)
{
    extern __shared__ float sm[];
    float* sW = sm;                  // [64][128]
    float* sA = sW + IN_DIM * HID;   // [128][68]
    float* sB = sA + MT * KSS;

    int tx = threadIdx.x;
    for (int i = tx; i < IN_DIM * HID / 4; i += 256)
        ((float4*)sW)[i] = ((const float4*)w1r)[i];
    if (tx < HID) sB[tx] = b1l[tx];

    int nb = blockIdx.x * MT;
    for (int i = tx; i < MT * 16; i += 256) {
        int row = i >> 4, q = i & 15;
        int n = nb + row;
        float4 vx = make_float4(0.f, 0.f, 0.f, 0.f);
        if (n < N_NODES) vx = ((const float4*)x)[n * 16 + q];
        *(float4*)(sA + row * KSS + q * 4) = vx;
    }
    __syncthreads();

    int c = tx & 7, r = tx >> 3;
    ull acc[4][8];
    #pragma unroll
    for (int j = 0; j < 8; j++) {
        ull b = ((const ull*)sB)[c + 8 * j];
        acc[0][j] = b; acc[1][j] = b; acc[2][j] = b; acc[3][j] = b;
    }

    const float* a0 = sA + (r * 4 + 0) * KSS;
    const float* a1 = sA + (r * 4 + 1) * KSS;
    const float* a2 = sA + (r * 4 + 2) * KSS;
    const float* a3 = sA + (r * 4 + 3) * KSS;

    GEMM_LOOP(IN_DIM)

    #pragma unroll
    for (int i = 0; i < 4; i++) {
        int n = nb + r * 4 + i;
        if (n < N_NODES) {
            ull* dst = (ull*)(g_h1pre + (size_t)n * HID);
            #pragma unroll
            for (int j = 0; j < 8; j++) dst[c + 8 * j] = acc[i][j];
        }
    }
}

__global__ void scan_tops_kernel() {
    __shared__ int s[256];
    int t = threadIdx.x;
    int v = (t < NCHUNK) ? g_chunk[t] : 0;
    s[t] = v;
    __syncthreads();
    for (int off = 1; off < 256; off <<= 1) {
        int add = (t >= off) ? s[t - off] : 0;
        __syncthreads();
        s[t] += add;
        __syncthreads();
    }
    if (t < NCHUNK) g_chunk[t] = s[t] - v;
}

__global__ void add_off_kernel() {
    int i = blockIdx.x * blockDim.x + threadIdx.x;
    if (i < N_NODES) {
        int rp = g_rowptr[i] + g_chunk[i / CHUNK];
        g_rowptr[i] = rp;
        g_pos[i] = rp;
    }
}

__global__ void fill_kernel(const int* __restrict__ ei) {
    int e = blockIdx.x * blockDim.x + threadIdx.x;
    if (e < N_EDGES) {
        int src = ei[e];
        int dst = ei[N_EDGES + e];
        int p = atomicAdd(&g_pos[dst], 1);
        g_col[p] = src;
    }
}

// ---------------- gather 1: warp per node, mean of x16[neighbors] -----------
__global__ __launch_bounds__(256) void gather1_kernel() {
    int warp = threadIdx.x >> 5, lane = threadIdx.x & 31;
    int n = blockIdx.x * 8 + warp;
    if (n >= N_NODES) return;
    int d = g_deg[n], st = g_rowptr[n];
    float ax = 0.f, ay = 0.f;
    for (int base = 0; base < d; base += 32) {
        int m = min(d - base, 32);
        int ci = (lane < m) ? g_col[st + base + lane] : 0;
        int j = 0;
        for (; j + 8 <= m; j += 8) {
            int ss[8];
            #pragma unroll
            for (int u = 0; u < 8; u++) ss[u] = __shfl_sync(0xffffffffu, ci, j + u);
            __half2 v[8];
            #pragma unroll
            for (int u = 0; u < 8; u++) v[u] = g_xh[ss[u] * 32 + lane];
            #pragma unroll
            for (int u = 0; u < 8; u++) {
                float2 f = __half22float2(v[u]);
                ax += f.x; ay += f.y;
            }
        }
        for (; j < m; j++) {
            int s = __shfl_sync(0xffffffffu, ci, j);
            float2 f = __half22float2(g_xh[s * 32 + lane]);
            ax += f.x; ay += f.y;
        }
    }
    float rc = 1.0f / fmaxf((float)d, 1.0f);
    ((float2*)g_agg1)[n * 32 + lane] = make_float2(ax * rc, ay * rc);
}

// ---------------- GEMM 1b: agg @ w1l + h1pre, L2norm, relu, BN stats --------
#define SMEMG1 ((IN_DIM*HID + MT*KSS + 2*HID) * 4)

__global__ __launch_bounds__(256, 2) void gemm1_kernel(
    const float* __restrict__ w1l)
{
    extern __shared__ float sm[];
    float* sW   = sm;                  // [64][128]
    float* sA   = sW + IN_DIM * HID;   // [128][68]
    float* sSum = sA + MT * KSS;
    float* sSq  = sSum + HID;

    int tx = threadIdx.x;
    for (int i = tx; i < IN_DIM * HID / 4; i += 256)
        ((float4*)sW)[i] = ((const float4*)w1l)[i];
    if (tx < HID) { sSum[tx] = 0.f; sSq[tx] = 0.f; }

    int nb = blockIdx.x * MT;
    for (int i = tx; i < MT * 16; i += 256) {
        int row = i >> 4, q = i & 15;
        int n = nb + row;
        float4 va = make_float4(0.f, 0.f, 0.f, 0.f);
        if (n < N_NODES) va = ((const float4*)g_agg1)[n * 16 + q];
        *(float4*)(sA + row * KSS + q * 4) = va;
    }
    __syncthreads();

    int c = tx & 7, r = tx >> 3;
    ull acc[4][8];
    #pragma unroll
    for (int i = 0; i < 4; i++) {
        int n = nb + r * 4 + i;
        const ull* src = (const ull*)(g_h1pre + (size_t)(n < N_NODES ? n : 0) * HID);
        #pragma unroll
        for (int j = 0; j < 8; j++) acc[i][j] = src[c + 8 * j];
    }

    const float* a0 = sA + (r * 4 + 0) * KSS;
    const float* a1 = sA + (r * 4 + 1) * KSS;
    const float* a2 = sA + (r * 4 + 2) * KSS;
    const float* a3 = sA + (r * 4 + 3) * KSS;

    GEMM_LOOP(IN_DIM)

    // epilogue: per-node L2 norm, relu, store h1 (fp32+fp16), BN col stats
    float cs[16], cq[16];
    #pragma unroll
    for (int t = 0; t < 16; t++) { cs[t] = 0.f; cq[t] = 0.f; }

    #pragma unroll
    for (int i = 0; i < 4; i++) {
        float2 p[8];
        float ss = 0.f;
        #pragma unroll
        for (int j = 0; j < 8; j++) {
            p[j] = unpack2(acc[i][j]);
            ss += p[j].x * p[j].x + p[j].y * p[j].y;
        }
        ss += __shfl_xor_sync(0xffffffffu, ss, 1);
        ss += __shfl_xor_sync(0xffffffffu, ss, 2);
        ss += __shfl_xor_sync(0xffffffffu, ss, 4);
        float inv = 1.0f / fmaxf(sqrtf(ss), 1e-12f);
        int n = nb + r * 4 + i;
        bool ok = (n < N_NODES);
        #pragma unroll
        for (int j = 0; j < 8; j++) {
            float hx = fmaxf(p[j].x * inv, 0.f);
            float hy = fmaxf(p[j].y * inv, 0.f);
            if (!ok) { hx = 0.f; hy = 0.f; }
            else {
                *(float2*)(g_h1 + (size_t)n * HID + (c + 8 * j) * 2) = make_float2(hx, hy);
                g_h1h[n * 64 + c + 8 * j] = __floats2half2_rn(hx, hy);
            }
            cs[2 * j] += hx; cs[2 * j + 1] += hy;
            cq[2 * j] += hx * hx; cq[2 * j + 1] += hy * hy;
        }
    }
    #pragma unroll
    for (int t = 0; t < 16; t++) {
        cs[t] += __shfl_xor_sync(0xffffffffu, cs[t], 8);
        cs[t] += __shfl_xor_sync(0xffffffffu, cs[t], 16);
        cq[t] += __shfl_xor_sync(0xffffffffu, cq[t], 8);
        cq[t] += __shfl_xor_sync(0xffffffffu, cq[t], 16);
    }
    if ((tx & 31) < 8) {
        #pragma unroll
        for (int j = 0; j < 8; j++) {
            atomicAdd(&sSum[(c + 8 * j) * 2],     cs[2 * j]);
            atomicAdd(&sSum[(c + 8 * j) * 2 + 1], cs[2 * j + 1]);
            atomicAdd(&sSq[(c + 8 * j) * 2],      cq[2 * j]);
            atomicAdd(&sSq[(c + 8 * j) * 2 + 1],  cq[2 * j + 1]);
        }
    }
    __syncthreads();
    if (tx < HID) {
        atomicAdd(&g_bnsum[tx], sSum[tx]);
        atomicAdd(&g_bnsq[tx], sSq[tx]);
    }
}

// ---------------- BN finalize ----------------
__global__ void bn_finalize_kernel(const float* __restrict__ gamma,
                                   const float* __restrict__ beta)
{
    int j = threadIdx.x;
    if (j < HID) {
        float mean = g_bnsum[j] / (float)N_NODES;
        float var  = g_bnsq[j] / (float)N_NODES - mean * mean;
        float inv  = rsqrtf(var + 1e-5f);
        float sc   = gamma[j] * inv;
        g_bnscale[j] = sc;
        g_bnshift[j] = beta[j] - mean * sc;
    }
}

// ---------------- gather 2: warp per node, fp16 h1, BN fused ----------------
__global__ __launch_bounds__(256) void gather2_kernel() {
    int warp = threadIdx.x >> 5, lane = threadIdx.x & 31;
    int n = blockIdx.x * 8 + warp;
    if (n >= N_NODES) return;
    int d = g_deg[n], st = g_rowptr[n];
    const uint2* h2p = (const uint2*)g_h1h;
    float4 acc = make_float4(0.f, 0.f, 0.f, 0.f);
    for (int base = 0; base < d; base += 32) {
        int m = min(d - base, 32);
        int ci = (lane < m) ? g_col[st + base + lane] : 0;
        int j = 0;
        for (; j + 4 <= m; j += 4) {
            int ss[4];
            #pragma unroll
            for (int u = 0; u < 4; u++) ss[u] = __shfl_sync(0xffffffffu, ci, j + u);
            uint2 rv[4];
            #pragma unroll
            for (int u = 0; u < 4; u++) rv[u] = h2p[ss[u] * 32 + lane];
            #pragma unroll
            for (int u = 0; u < 4; u++) {
                union { uint2 u2; __half2 h[2]; } pk; pk.u2 = rv[u];
                float2 f0 = __half22float2(pk.h[0]);
                float2 f1 = __half22float2(pk.h[1]);
                acc.x += f0.x; acc.y += f0.y; acc.z += f1.x; acc.w += f1.y;
            }
        }
        for (; j < m; j++) {
            int s = __shfl_sync(0xffffffffu, ci, j);
            union { uint2 u2; __half2 h[2]; } pk; pk.u2 = h2p[s * 32 + lane];
            float2 f0 = __half22float2(pk.h[0]);
            float2 f1 = __half22float2(pk.h[1]);
            acc.x += f0.x; acc.y += f0.y; acc.z += f1.x; acc.w += f1.y;
        }
    }
    float rc = 1.0f / fmaxf((float)d, 1.0f);
    float flag = (d > 0) ? 1.0f : 0.0f;
    float4 sc = ((const float4*)g_bnscale)[lane];
    float4 sh = ((const float4*)g_bnshift)[lane];
    float4 ag;
    ag.x = sc.x * acc.x * rc + sh.x * flag;
    ag.y = sc.y * acc.y * rc + sh.y * flag;
    ag.z = sc.z * acc.z * rc + sh.z * flag;
    ag.w = sc.w * acc.w * rc + sh.w * flag;
    ((float4*)g_agg2)[n * 32 + lane] = ag;
}

// ---------------- GEMM 2: [agg2|BN(h1)] @ [w2l;w2r] + b, L2norm, FC ---------
#define KS1 132
#define SMEMG2 ((HID*HID + MT*KS1 + HID*OUT_DIM + 3*HID + OUT_DIM) * 4)

__global__ __launch_bounds__(256) void gemm2_kernel(
    const float* __restrict__ w2l,
    const float* __restrict__ b2l,
    const float* __restrict__ w2r,
    const float* __restrict__ wfc,
    const float* __restrict__ bfc,
    float* __restrict__ out)
{
    extern __shared__ float sm[];
    float* sW   = sm;                    // [128][128] streamed: w2l then w2r
    float* sA   = sW + HID * HID;        // [128][132] streamed: agg2 then BN(h1)
    float* sWfc = sA + MT * KS1;         // [128][16]
    float* sB   = sWfc + HID * OUT_DIM;
    float* sSc  = sB + HID;
    float* sSh  = sSc + HID;
    float* sBfc = sSh + HID;

    int tx = threadIdx.x;
    if (tx < HID) {
        sB[tx]  = b2l[tx];
        sSc[tx] = g_bnscale[tx];
        sSh[tx] = g_bnshift[tx];
    }
    if (tx < OUT_DIM) sBfc[tx] = bfc[tx];
    for (int i = tx; i < HID * HID / 4; i += 256)
        ((float4*)sW)[i] = ((const float4*)w2l)[i];
    for (int i = tx; i < HID * OUT_DIM / 4; i += 256)
        ((float4*)sWfc)[i] = ((const float4*)wfc)[i];

    int nb = blockIdx.x * MT;
    for (int i = tx; i < MT * 32; i += 256) {
        int row = i >> 5, q = i & 31;
        int n = nb + row;
        float4 v = make_float4(0.f, 0.f, 0.f, 0.f);
        if (n < N_NODES) v = ((const float4*)g_agg2)[n * 32 + q];
        *(float4*)(sA + row * KS1 + q * 4) = v;
    }
    __syncthreads();

    int c = tx & 7, r = tx >> 3;
    ull acc[4][8];
    #pragma unroll
    for (int j = 0; j < 8; j++) {
        ull b = ((const ull*)sB)[c + 8 * j];
        acc[0][j] = b; acc[1][j] = b; acc[2][j] = b; acc[3][j] = b;
    }

    #pragma unroll
    for (int pass = 0; pass < 2; pass++) {
        if (pass == 1) {
            __syncthreads();
            for (int i = tx; i < HID * HID / 4; i += 256)
                ((float4*)sW)[i] = ((const float4*)w2r)[i];
            for (int i = tx; i < MT * 32; i += 256) {
                int row = i >> 5, q = i & 31;
                int n = nb + row;
                float4 h = make_float4(0.f, 0.f, 0.f, 0.f);
                if (n < N_NODES) h = ((const float4*)g_h1)[n * 32 + q];
                float4 sc = ((const float4*)sSc)[q];
                float4 sh = ((const float4*)sSh)[q];
                float4 v;
                v.x = sc.x * h.x + sh.x;
                v.y = sc.y * h.y + sh.y;
                v.z = sc.z * h.z + sh.z;
                v.w = sc.w * h.w + sh.w;
                *(float4*)(sA + row * KS1 + q * 4) = v;
            }
            __syncthreads();
        }
        const float* a0 = sA + (r * 4 + 0) * KS1;
        const float* a1 = sA + (r * 4 + 1) * KS1;
        const float* a2 = sA + (r * 4 + 2) * KS1;
        const float* a3 = sA + (r * 4 + 3) * KS1;

        GEMM_LOOP(HID)
    }

    // L2 normalize each node row
    float2 p[4][8];
    #pragma unroll
    for (int i = 0; i < 4; i++) {
        float ss = 0.f;
        #pragma unroll
        for (int j = 0; j < 8; j++) {
            p[i][j] = unpack2(acc[i][j]);
            ss += p[i][j].x * p[i][j].x + p[i][j].y * p[i][j].y;
        }
        ss += __shfl_xor_sync(0xffffffffu, ss, 1);
        ss += __shfl_xor_sync(0xffffffffu, ss, 2);
        ss += __shfl_xor_sync(0xffffffffu, ss, 4);
        float inv = 1.0f / fmaxf(sqrtf(ss), 1e-12f);
        #pragma unroll
        for (int j = 0; j < 8; j++) { p[i][j].x *= inv; p[i][j].y *= inv; }
    }
    __syncthreads();

    float* sH = sA;    // [128][132]
    #pragma unroll
    for (int i = 0; i < 4; i++)
        #pragma unroll
        for (int j = 0; j < 8; j++)
            *(float2*)(sH + (r * 4 + i) * KS1 + (c + 8 * j) * 2) = p[i][j];
    __syncthreads();

    int node = tx >> 1;
    int half = tx & 1;
    int n = nb + node;
    if (n < N_NODES) {
        float y[8];
        #pragma unroll
        for (int t = 0; t < 8; t++) y[t] = sBfc[half * 8 + t];
        const float* h = sH + node * KS1;
        #pragma unroll 4
        for (int j2 = 0; j2 < HID; j2++) {
            float hv = h[j2];
            float4 w0 = *(const float4*)(sWfc + j2 * OUT_DIM + half * 8);
            float4 w1 = *(const float4*)(sWfc + j2 * OUT_DIM + half * 8 + 4);
            y[0] += hv * w0.x; y[1] += hv * w0.y; y[2] += hv * w0.z; y[3] += hv * w0.w;
            y[4] += hv * w1.x; y[5] += hv * w1.y; y[6] += hv * w1.z; y[7] += hv * w1.w;
        }
        *(float4*)(out + (size_t)n * OUT_DIM + half * 8)     = make_float4(y[0], y[1], y[2], y[3]);
        *(float4*)(out + (size_t)n * OUT_DIM + half * 8 + 4) = make_float4(y[4], y[5], y[6], y[7]);
    }
}

// ---------------- launch ----------------------------------------------------
extern "C" void kernel_launch(void* const* d_in, const int* in_sizes, int n_in,
                              void* d_out, int out_size)
{
    const float* x     = (const float*)d_in[0];
    const int*   ei    = (const int*)d_in[1];
    const float* w1l   = (const float*)d_in[2];
    const float* b1l   = (const float*)d_in[3];
    const float* w1r   = (const float*)d_in[4];
    const float* gamma = (const float*)d_in[5];
    const float* beta  = (const float*)d_in[6];
    const float* w2l   = (const float*)d_in[7];
    const float* b2l   = (const float*)d_in[8];
    const float* w2r   = (const float*)d_in[9];
    const float* wfc   = (const float*)d_in[10];
    const float* bfc   = (const float*)d_in[11];
    float* out = (float*)d_out;

    cudaFuncSetAttribute(gemm_self_kernel, cudaFuncAttributeMaxDynamicSharedMemorySize, SMEMS);
    cudaFuncSetAttribute(gemm1_kernel, cudaFuncAttributeMaxDynamicSharedMemorySize, SMEMG1);
    cudaFuncSetAttribute(gemm2_kernel, cudaFuncAttributeMaxDynamicSharedMemorySize, SMEMG2);

    int ng = (N_NODES + 255) / 256;        // 391
    int eg = (N_EDGES + 255) / 256;        // 6250
    int gg = (N_NODES + 7) / 8;            // 12500
    int mg = (N_NODES + MT - 1) / MT;      // 782

    zero_kernel<<<eg, 256>>>(x);                        // #1
    hist_kernel<<<eg, 256>>>(ei);                       // #2
    scan_chunk_kernel<<<NCHUNK, CHUNK>>>();             // #3
    gemm_self_kernel<<<mg, 256, SMEMS>>>(x, w1r, b1l);  // #4  <-- profiled slot
    scan_tops_kernel<<<1, 256>>>();                     // #5
    add_off_kernel<<<ng, 256>>>();                      // #6
    fill_kernel<<<eg, 256>>>(ei);                       // #7
    gather1_kernel<<<gg, 256>>>();                      // #8
    gemm1_kernel<<<mg, 256, SMEMG1>>>(w1l);             // #9
    bn_finalize_kernel<<<1, 128>>>(gamma, beta);        // #10
    gather2_kernel<<<gg, 256>>>();                      // #11
    gemm2_kernel<<<mg, 256, SMEMG2>>>(w2l, b2l, w2r, wfc, bfc, out);  // #12
}